// round 2
// baseline (speedup 1.0000x reference)
#include <cuda_runtime.h>
#include <cuda_bf16.h>

// WeightAndSum: gated segment sum.
//   logits = feats @ W + b          (atom logits are an output, pre-sigmoid)
//   w      = sigmoid(logits)
//   out[g] = sum_{rows r with seg[r]==g} w[r] * feats[r]
//
// Segments are SORTED, so each warp processes a contiguous chunk of rows,
// accumulates the current segment in registers, and flushes with atomicAdd
// only on segment change / chunk end.
//
// Layout: warp-per-chunk, lane l owns columns [4l, 4l+4) as a float4.
// Row loop is software-pipelined 1 deep to overlap the next row's LDG with
// the current row's shuffle-reduce + FMA work.

#define F_DIM 128
#define F_VEC 32          // F_DIM / 4 float4s per row

__global__ __launch_bounds__(256, 8)
void was_kernel(
    // atom job
    const float* __restrict__ a_feats, const float* __restrict__ a_W,
    const float* __restrict__ a_b, const int* __restrict__ a_seg,
    float* __restrict__ a_out, float* __restrict__ a_logits,
    int a_n, int a_rpw, int a_blocks,
    // vir job
    const float* __restrict__ v_feats, const float* __restrict__ v_W,
    const float* __restrict__ v_b, const int* __restrict__ v_seg,
    float* __restrict__ v_out,
    int v_n, int v_rpw)
{
    const float* feats;
    const float* Wp;
    const float* bp;
    const int*   seg;
    float*       outp;
    float*       logits;
    int n, rpw, block_in_job;

    if (blockIdx.x < (unsigned)a_blocks) {
        feats = a_feats; Wp = a_W; bp = a_b; seg = a_seg;
        outp = a_out; logits = a_logits; n = a_n; rpw = a_rpw;
        block_in_job = blockIdx.x;
    } else {
        feats = v_feats; Wp = v_W; bp = v_b; seg = v_seg;
        outp = v_out; logits = nullptr; n = v_n; rpw = v_rpw;
        block_in_job = blockIdx.x - a_blocks;
    }

    const int warp_in_block = threadIdx.x >> 5;
    const int lane = threadIdx.x & 31;
    const int gwarp = block_in_job * (blockDim.x >> 5) + warp_in_block;

    long start = (long)gwarp * rpw;
    if (start >= n) return;
    long end = start + rpw;
    if (end > n) end = n;

    // Gate weights held in registers (one float4 per lane)
    const float4 Wv = reinterpret_cast<const float4*>(Wp)[lane];
    const float bias = bp[0];

    const float4* frows = reinterpret_cast<const float4*>(feats);

    float4 acc = make_float4(0.f, 0.f, 0.f, 0.f);
    int cur_seg = __ldg(&seg[start]);

    // ---- software pipeline: prefetch row `start` ----
    float4 f_cur = frows[start * F_VEC + lane];
    int    s_cur = cur_seg;

    for (long r = start; r < end; ++r) {
        // issue next row's loads before consuming current row
        float4 f_nxt;
        int    s_nxt = 0;
        if (r + 1 < end) {
            f_nxt = frows[(r + 1) * F_VEC + lane];
            s_nxt = __ldg(&seg[r + 1]);
        }

        float4 f = f_cur;
        int    s = s_cur;

        // per-row gate: warp-wide dot(feat, W) + b -> sigmoid
        float p = f.x * Wv.x + f.y * Wv.y + f.z * Wv.z + f.w * Wv.w;
        p += __shfl_xor_sync(0xFFFFFFFFu, p, 16);
        p += __shfl_xor_sync(0xFFFFFFFFu, p, 8);
        p += __shfl_xor_sync(0xFFFFFFFFu, p, 4);
        p += __shfl_xor_sync(0xFFFFFFFFu, p, 2);
        p += __shfl_xor_sync(0xFFFFFFFFu, p, 1);
        float logit = p + bias;

        if (logits != nullptr && lane == 0) {
            logits[r] = logit;  // pre-sigmoid, matching reference
        }

        float w = 1.0f / (1.0f + __expf(-logit));

        if (s != cur_seg) {
            float* o = outp + (long)cur_seg * F_DIM + lane * 4;
            atomicAdd(o + 0, acc.x);
            atomicAdd(o + 1, acc.y);
            atomicAdd(o + 2, acc.z);
            atomicAdd(o + 3, acc.w);
            acc = make_float4(0.f, 0.f, 0.f, 0.f);
            cur_seg = s;
        }

        acc.x += w * f.x;
        acc.y += w * f.y;
        acc.z += w * f.z;
        acc.w += w * f.w;

        f_cur = f_nxt;
        s_cur = s_nxt;
    }

    // final flush
    float* o = outp + (long)cur_seg * F_DIM + lane * 4;
    atomicAdd(o + 0, acc.x);
    atomicAdd(o + 1, acc.y);
    atomicAdd(o + 2, acc.z);
    atomicAdd(o + 3, acc.w);
}

extern "C" void kernel_launch(void* const* d_in, const int* in_sizes, int n_in,
                              void* d_out, int out_size)
{
    const float* atom_feats = (const float*)d_in[0];
    const float* vir_feats  = (const float*)d_in[1];
    const float* W_atom     = (const float*)d_in[2];
    const float* b_atom     = (const float*)d_in[3];
    const float* W_vir      = (const float*)d_in[4];
    const float* b_vir      = (const float*)d_in[5];
    const int*   atom_seg   = (const int*)d_in[6];
    const int*   vir_seg    = (const int*)d_in[7];

    const int n_atom = in_sizes[0] / F_DIM;
    const int n_vir  = in_sizes[1] / F_DIM;
    // out layout: [G,128] atom sums | [G,128] vir sums | [n_atom] logits
    const int G = (out_size - n_atom) / (2 * F_DIM);

    float* out       = (float*)d_out;
    float* out_atom  = out;
    float* out_vir   = out + (size_t)G * F_DIM;
    float* logits    = out + (size_t)2 * G * F_DIM;

    // zero the two segment-sum regions (logits region is fully overwritten)
    cudaMemsetAsync(out, 0, (size_t)2 * G * F_DIM * sizeof(float), 0);

    const int threads = 256;
    const int wpb = threads / 32;

    // atom: ~6400 warps -> ~128 rows/warp (avg segment ~50 rows)
    int a_blocks = 800;
    int a_warps  = a_blocks * wpb;
    int a_rpw    = (n_atom + a_warps - 1) / a_warps;

    // vir: 2048 warps -> ~32 rows/warp (avg segment ~4 rows)
    int v_blocks = 256;
    int v_warps  = v_blocks * wpb;
    int v_rpw    = (n_vir + v_warps - 1) / v_warps;

    was_kernel<<<a_blocks + v_blocks, threads, 0, 0>>>(
        atom_feats, W_atom, b_atom, atom_seg, out_atom, logits,
        n_atom, a_rpw, a_blocks,
        vir_feats, W_vir, b_vir, vir_seg, out_vir,
        n_vir, v_rpw);
}

// round 3
// speedup vs baseline: 1.3674x; 1.3674x over previous
#include <cuda_runtime.h>
#include <cuda_bf16.h>

// WeightAndSum: gated segment sum, 4-row-unrolled warp-per-chunk version.
//   logits = feats @ W + b          (atom logits output, pre-sigmoid)
//   w      = sigmoid(logits)
//   out[g] = sum_{seg[r]==g} w[r] * feats[r]
//
// Segments are SORTED: each warp owns a contiguous 4-aligned chunk of rows,
// accumulates the current segment in registers, flushes via atomicAdd only on
// segment change. 4 rows per iteration interleaves the 4 shuffle-reduce
// chains (the round-2 bottleneck) and gives MLP=4 on the feature loads.

#define F_DIM 128
#define F_VEC 32          // float4s per row

__global__ __launch_bounds__(256)
void was_kernel(
    // atom job
    const float* __restrict__ a_feats, const float* __restrict__ a_W,
    const float* __restrict__ a_b, const int* __restrict__ a_seg,
    float* __restrict__ a_out, float* __restrict__ a_logits,
    int a_n, int a_rpw, int a_blocks,
    // vir job
    const float* __restrict__ v_feats, const float* __restrict__ v_W,
    const float* __restrict__ v_b, const int* __restrict__ v_seg,
    float* __restrict__ v_out,
    int v_n, int v_rpw)
{
    const float* feats;
    const float* Wp;
    const float* bp;
    const int*   seg;
    float*       outp;
    float*       logits;
    int n, rpw, block_in_job;

    if (blockIdx.x < (unsigned)a_blocks) {
        feats = a_feats; Wp = a_W; bp = a_b; seg = a_seg;
        outp = a_out; logits = a_logits; n = a_n; rpw = a_rpw;
        block_in_job = blockIdx.x;
    } else {
        feats = v_feats; Wp = v_W; bp = v_b; seg = v_seg;
        outp = v_out; logits = nullptr; n = v_n; rpw = v_rpw;
        block_in_job = blockIdx.x - a_blocks;
    }

    const int lane  = threadIdx.x & 31;
    const int gwarp = block_in_job * (blockDim.x >> 5) + (threadIdx.x >> 5);

    long start = (long)gwarp * rpw;          // rpw is a multiple of 4
    if (start >= n) return;
    long end = start + rpw;
    if (end > n) end = n;

    const float4 Wv  = reinterpret_cast<const float4*>(Wp)[lane];
    const float bias = bp[0];
    const float4* frows = reinterpret_cast<const float4*>(feats);

    float4 acc = make_float4(0.f, 0.f, 0.f, 0.f);
    int cur_seg = __ldg(&seg[start]);

    long r = start;
    long end4 = start + ((end - start) & ~3L);

    for (; r < end4; r += 4) {
        // 4 independent feature loads (MLP=4) + one int4 segment load
        float4 f0 = frows[(r + 0) * F_VEC + lane];
        float4 f1 = frows[(r + 1) * F_VEC + lane];
        float4 f2 = frows[(r + 2) * F_VEC + lane];
        float4 f3 = frows[(r + 3) * F_VEC + lane];
        int4 sv = *reinterpret_cast<const int4*>(seg + r);

        // 4 partial dots
        float p0 = f0.x * Wv.x + f0.y * Wv.y + f0.z * Wv.z + f0.w * Wv.w;
        float p1 = f1.x * Wv.x + f1.y * Wv.y + f1.z * Wv.z + f1.w * Wv.w;
        float p2 = f2.x * Wv.x + f2.y * Wv.y + f2.z * Wv.z + f2.w * Wv.w;
        float p3 = f3.x * Wv.x + f3.y * Wv.y + f3.z * Wv.z + f3.w * Wv.w;

        // interleaved butterfly reduce: 4 chains overlap their SHFL latency
        #pragma unroll
        for (int d = 16; d > 0; d >>= 1) {
            p0 += __shfl_xor_sync(0xFFFFFFFFu, p0, d);
            p1 += __shfl_xor_sync(0xFFFFFFFFu, p1, d);
            p2 += __shfl_xor_sync(0xFFFFFFFFu, p2, d);
            p3 += __shfl_xor_sync(0xFFFFFFFFu, p3, d);
        }

        float l0 = p0 + bias, l1 = p1 + bias, l2 = p2 + bias, l3 = p3 + bias;

        if (logits != nullptr && lane == 0) {
            // r is 4-aligned -> 16B-aligned vector store of the 4 logits
            *reinterpret_cast<float4*>(logits + r) = make_float4(l0, l1, l2, l3);
        }

        float w0 = 1.0f / (1.0f + __expf(-l0));
        float w1 = 1.0f / (1.0f + __expf(-l1));
        float w2 = 1.0f / (1.0f + __expf(-l2));
        float w3 = 1.0f / (1.0f + __expf(-l3));

        // sequential segment handling (sorted ids; changes are rare)
        #pragma unroll
        for (int k = 0; k < 4; ++k) {
            int s     = (k == 0) ? sv.x : (k == 1) ? sv.y : (k == 2) ? sv.z : sv.w;
            float w   = (k == 0) ? w0   : (k == 1) ? w1   : (k == 2) ? w2   : w3;
            float4 f  = (k == 0) ? f0   : (k == 1) ? f1   : (k == 2) ? f2   : f3;
            if (s != cur_seg) {
                float* o = outp + (long)cur_seg * F_DIM + lane * 4;
                atomicAdd(o + 0, acc.x);
                atomicAdd(o + 1, acc.y);
                atomicAdd(o + 2, acc.z);
                atomicAdd(o + 3, acc.w);
                acc = make_float4(0.f, 0.f, 0.f, 0.f);
                cur_seg = s;
            }
            acc.x += w * f.x;
            acc.y += w * f.y;
            acc.z += w * f.z;
            acc.w += w * f.w;
        }
    }

    // scalar tail (only if chunk length not a multiple of 4)
    for (; r < end; ++r) {
        float4 f = frows[r * F_VEC + lane];
        int s = __ldg(&seg[r]);
        float p = f.x * Wv.x + f.y * Wv.y + f.z * Wv.z + f.w * Wv.w;
        #pragma unroll
        for (int d = 16; d > 0; d >>= 1) p += __shfl_xor_sync(0xFFFFFFFFu, p, d);
        float logit = p + bias;
        if (logits != nullptr && lane == 0) logits[r] = logit;
        float w = 1.0f / (1.0f + __expf(-logit));
        if (s != cur_seg) {
            float* o = outp + (long)cur_seg * F_DIM + lane * 4;
            atomicAdd(o + 0, acc.x);
            atomicAdd(o + 1, acc.y);
            atomicAdd(o + 2, acc.z);
            atomicAdd(o + 3, acc.w);
            acc = make_float4(0.f, 0.f, 0.f, 0.f);
            cur_seg = s;
        }
        acc.x += w * f.x;
        acc.y += w * f.y;
        acc.z += w * f.z;
        acc.w += w * f.w;
    }

    // final flush
    float* o = outp + (long)cur_seg * F_DIM + lane * 4;
    atomicAdd(o + 0, acc.x);
    atomicAdd(o + 1, acc.y);
    atomicAdd(o + 2, acc.z);
    atomicAdd(o + 3, acc.w);
}

extern "C" void kernel_launch(void* const* d_in, const int* in_sizes, int n_in,
                              void* d_out, int out_size)
{
    const float* atom_feats = (const float*)d_in[0];
    const float* vir_feats  = (const float*)d_in[1];
    const float* W_atom     = (const float*)d_in[2];
    const float* b_atom     = (const float*)d_in[3];
    const float* W_vir      = (const float*)d_in[4];
    const float* b_vir      = (const float*)d_in[5];
    const int*   atom_seg   = (const int*)d_in[6];
    const int*   vir_seg    = (const int*)d_in[7];

    const int n_atom = in_sizes[0] / F_DIM;
    const int n_vir  = in_sizes[1] / F_DIM;
    // out layout: [G,128] atom sums | [G,128] vir sums | [n_atom] logits
    const int G = (out_size - n_atom) / (2 * F_DIM);

    float* out       = (float*)d_out;
    float* out_atom  = out;
    float* out_vir   = out + (size_t)G * F_DIM;
    float* logits    = out + (size_t)2 * G * F_DIM;

    cudaMemsetAsync(out, 0, (size_t)2 * G * F_DIM * sizeof(float), 0);

    const int threads = 256;
    const int wpb = threads / 32;

    // atom: 1600 blocks * 8 warps -> 64 rows/warp (4-aligned)
    int a_blocks = 1600;
    int a_rpw = (n_atom + a_blocks * wpb - 1) / (a_blocks * wpb);
    a_rpw = (a_rpw + 3) & ~3;

    // vir: 512 blocks * 8 warps -> 16 rows/warp (4-aligned)
    int v_blocks = 512;
    int v_rpw = (n_vir + v_blocks * wpb - 1) / (v_blocks * wpb);
    v_rpw = (v_rpw + 3) & ~3;

    was_kernel<<<a_blocks + v_blocks, threads, 0, 0>>>(
        atom_feats, W_atom, b_atom, atom_seg, out_atom, logits,
        n_atom, a_rpw, a_blocks,
        vir_feats, W_vir, b_vir, vir_seg, out_vir,
        n_vir, v_rpw);
}

// round 5
// speedup vs baseline: 1.5380x; 1.1248x over previous
#include <cuda_runtime.h>
#include <cuda_bf16.h>

// WeightAndSum: gated segment sum. Single-wave persistent layout,
// 4-row groups with depth-2 software pipeline (8 outstanding LDG.128/warp).
//   logits = feats @ W + b   (atom logits output, pre-sigmoid)
//   out[g] = sum_{seg[r]==g} sigmoid(logit_r) * feats[r]
// Sorted segments -> register accumulation, atomic flush on segment change.

#define F_DIM 128
#define F_VEC 32          // float4s per row

__global__ __launch_bounds__(256, 3)
void was_kernel(
    // atom job
    const float* __restrict__ a_feats, const float* __restrict__ a_W,
    const float* __restrict__ a_b, const int* __restrict__ a_seg,
    float* __restrict__ a_out, float* __restrict__ a_logits,
    int a_n, int a_rpw, int a_blocks,
    // vir job
    const float* __restrict__ v_feats, const float* __restrict__ v_W,
    const float* __restrict__ v_b, const int* __restrict__ v_seg,
    float* __restrict__ v_out,
    int v_n, int v_rpw)
{
    const float* feats;
    const float* Wp;
    const float* bp;
    const int*   seg;
    float*       outp;
    float*       logits;
    int n, rpw, block_in_job;

    if (blockIdx.x < (unsigned)a_blocks) {
        feats = a_feats; Wp = a_W; bp = a_b; seg = a_seg;
        outp = a_out; logits = a_logits; n = a_n; rpw = a_rpw;
        block_in_job = blockIdx.x;
    } else {
        feats = v_feats; Wp = v_W; bp = v_b; seg = v_seg;
        outp = v_out; logits = nullptr; n = v_n; rpw = v_rpw;
        block_in_job = blockIdx.x - a_blocks;
    }

    const int lane  = threadIdx.x & 31;
    const int gwarp = block_in_job * (blockDim.x >> 5) + (threadIdx.x >> 5);

    long start = (long)gwarp * rpw;          // rpw is a multiple of 4
    if (start >= n) return;
    long end = start + rpw;
    if (end > n) end = n;                    // n is a multiple of 4

    const float4 Wv  = reinterpret_cast<const float4*>(Wp)[lane];
    const float bias = bp[0];
    const float4* frows = reinterpret_cast<const float4*>(feats);

    float4 acc = make_float4(0.f, 0.f, 0.f, 0.f);
    int cur_seg = __ldg(&seg[start]);

    // ---- depth-2 pipeline: prefetch first 4-row group ----
    float4 f0 = __ldcs(&frows[(start + 0) * F_VEC + lane]);
    float4 f1 = __ldcs(&frows[(start + 1) * F_VEC + lane]);
    float4 f2 = __ldcs(&frows[(start + 2) * F_VEC + lane]);
    float4 f3 = __ldcs(&frows[(start + 3) * F_VEC + lane]);
    int4  sv  = *reinterpret_cast<const int4*>(seg + start);

    for (long r = start; r < end; r += 4) {
        // prefetch next group before consuming current
        float4 g0, g1, g2, g3;
        int4 sn;
        bool more = (r + 4 < end);
        if (more) {
            g0 = __ldcs(&frows[(r + 4) * F_VEC + lane]);
            g1 = __ldcs(&frows[(r + 5) * F_VEC + lane]);
            g2 = __ldcs(&frows[(r + 6) * F_VEC + lane]);
            g3 = __ldcs(&frows[(r + 7) * F_VEC + lane]);
            sn = *reinterpret_cast<const int4*>(seg + r + 4);
        }

        // 4 partial dots
        float p0 = f0.x * Wv.x + f0.y * Wv.y + f0.z * Wv.z + f0.w * Wv.w;
        float p1 = f1.x * Wv.x + f1.y * Wv.y + f1.z * Wv.z + f1.w * Wv.w;
        float p2 = f2.x * Wv.x + f2.y * Wv.y + f2.z * Wv.z + f2.w * Wv.w;
        float p3 = f3.x * Wv.x + f3.y * Wv.y + f3.z * Wv.z + f3.w * Wv.w;

        // interleaved butterfly reduce (4 chains overlap SHFL latency)
        #pragma unroll
        for (int d = 16; d > 0; d >>= 1) {
            p0 += __shfl_xor_sync(0xFFFFFFFFu, p0, d);
            p1 += __shfl_xor_sync(0xFFFFFFFFu, p1, d);
            p2 += __shfl_xor_sync(0xFFFFFFFFu, p2, d);
            p3 += __shfl_xor_sync(0xFFFFFFFFu, p3, d);
        }

        float l0 = p0 + bias, l1 = p1 + bias, l2 = p2 + bias, l3 = p3 + bias;

        if (logits != nullptr && lane == 0) {
            __stcs(reinterpret_cast<float4*>(logits + r),
                   make_float4(l0, l1, l2, l3));
        }

        float w0 = 1.0f / (1.0f + __expf(-l0));
        float w1 = 1.0f / (1.0f + __expf(-l1));
        float w2 = 1.0f / (1.0f + __expf(-l2));
        float w3 = 1.0f / (1.0f + __expf(-l3));

        // sequential segment handling (sorted; changes rare)
        #pragma unroll
        for (int k = 0; k < 4; ++k) {
            int s     = (k == 0) ? sv.x : (k == 1) ? sv.y : (k == 2) ? sv.z : sv.w;
            float w   = (k == 0) ? w0   : (k == 1) ? w1   : (k == 2) ? w2   : w3;
            float4 f  = (k == 0) ? f0   : (k == 1) ? f1   : (k == 2) ? f2   : f3;
            if (s != cur_seg) {
                float* o = outp + (long)cur_seg * F_DIM + lane * 4;
                atomicAdd(o + 0, acc.x);
                atomicAdd(o + 1, acc.y);
                atomicAdd(o + 2, acc.z);
                atomicAdd(o + 3, acc.w);
                acc = make_float4(0.f, 0.f, 0.f, 0.f);
                cur_seg = s;
            }
            acc.x += w * f.x;
            acc.y += w * f.y;
            acc.z += w * f.z;
            acc.w += w * f.w;
        }

        f0 = g0; f1 = g1; f2 = g2; f3 = g3; sv = sn;
    }

    // final flush
    float* o = outp + (long)cur_seg * F_DIM + lane * 4;
    atomicAdd(o + 0, acc.x);
    atomicAdd(o + 1, acc.y);
    atomicAdd(o + 2, acc.z);
    atomicAdd(o + 3, acc.w);
}

extern "C" void kernel_launch(void* const* d_in, const int* in_sizes, int n_in,
                              void* d_out, int out_size)
{
    const float* atom_feats = (const float*)d_in[0];
    const float* vir_feats  = (const float*)d_in[1];
    const float* W_atom     = (const float*)d_in[2];
    const float* b_atom     = (const float*)d_in[3];
    const float* W_vir      = (const float*)d_in[4];
    const float* b_vir      = (const float*)d_in[5];
    const int*   atom_seg   = (const int*)d_in[6];
    const int*   vir_seg    = (const int*)d_in[7];

    const int n_atom = in_sizes[0] / F_DIM;
    const int n_vir  = in_sizes[1] / F_DIM;
    // out layout: [G,128] atom sums | [G,128] vir sums | [n_atom] logits
    const int G = (out_size - n_atom) / (2 * F_DIM);

    float* out       = (float*)d_out;
    float* out_atom  = out;
    float* out_vir   = out + (size_t)G * F_DIM;
    float* logits    = out + (size_t)2 * G * F_DIM;

    cudaMemsetAsync(out, 0, (size_t)2 * G * F_DIM * sizeof(float), 0);

    // Single wave: 148 SMs * 3 blocks/SM (launch_bounds(256,3))
    const int threads = 256;
    const int wpb = threads / 32;
    const int total_blocks = 148 * 3;

    // split blocks proportional to row counts, keep chunks 4-aligned
    long total_rows = (long)n_atom + n_vir;
    int a_blocks = (int)(((long)total_blocks * n_atom + total_rows - 1) / total_rows);
    if (a_blocks < 1) a_blocks = 1;
    if (a_blocks > total_blocks - 1) a_blocks = total_blocks - 1;
    int v_blocks = total_blocks - a_blocks;

    int a_rpw = (n_atom + a_blocks * wpb - 1) / (a_blocks * wpb);
    a_rpw = (a_rpw + 3) & ~3;
    int v_rpw = (n_vir + v_blocks * wpb - 1) / (v_blocks * wpb);
    v_rpw = (v_rpw + 3) & ~3;

    was_kernel<<<total_blocks, threads, 0, 0>>>(
        atom_feats, W_atom, b_atom, atom_seg, out_atom, logits,
        n_atom, a_rpw, a_blocks,
        vir_feats, W_vir, b_vir, vir_seg, out_vir,
        n_vir, v_rpw);
}